// round 2
// baseline (speedup 1.0000x reference)
#include <cuda_runtime.h>
#include <cuda_bf16.h>
#include <math.h>

// Problem constants
#define BATCH   2
#define SEQ     2048
#define DMODEL  1024
#define NHEADS  16
#define DHEAD   64
#define MROWS   (BATCH * SEQ)          // 4096
#define QKVN    (3 * DMODEL)           // 3072

// Scratch (device globals: allocation-free rule)
__device__ float g_qkv[(size_t)MROWS * QKVN];   // [4096, 3072]
__device__ float g_att[(size_t)MROWS * DMODEL]; // [B][H][S][Dh] flat == [4096,1024]

// ---------------------------------------------------------------------------
// GEMM (NT): C[M,N] = A[M,K] @ B[N,K]^T + bias[N]
// 128x128 block tile, BK=16, 256 threads, 8x8 per thread.
// M,N multiples of 128; K multiple of 16 (true for all three calls).
// ---------------------------------------------------------------------------
__global__ __launch_bounds__(256) void gemm_nt_bias(
    const float* __restrict__ A, const float* __restrict__ B,
    const float* __restrict__ bias, float* __restrict__ C,
    int M, int N, int K)
{
    __shared__ float As[16][132];   // [k][m], pad 4 to dodge store conflicts
    __shared__ float Bs[16][132];   // [k][n]

    const int tid = threadIdx.x;
    const int m0  = blockIdx.y * 128;
    const int n0  = blockIdx.x * 128;

    const int lr = tid >> 2;          // 0..63 load row
    const int lc = (tid & 3) << 2;    // 0,4,8,12 load k-col
    const int ty = tid >> 4;          // 0..15
    const int tx = tid & 15;          // 0..15

    float acc[8][8];
#pragma unroll
    for (int i = 0; i < 8; i++)
#pragma unroll
        for (int j = 0; j < 8; j++) acc[i][j] = 0.f;

    const float* Ap = A + (size_t)(m0 + lr) * K + lc;
    const float* Bp = B + (size_t)(n0 + lr) * K + lc;

    for (int k0 = 0; k0 < K; k0 += 16) {
#pragma unroll
        for (int h = 0; h < 2; h++) {
            float4 va = *(const float4*)(Ap + (size_t)h * 64 * K + k0);
            int r = lr + h * 64;
            As[lc + 0][r] = va.x; As[lc + 1][r] = va.y;
            As[lc + 2][r] = va.z; As[lc + 3][r] = va.w;
            float4 vb = *(const float4*)(Bp + (size_t)h * 64 * K + k0);
            Bs[lc + 0][r] = vb.x; Bs[lc + 1][r] = vb.y;
            Bs[lc + 2][r] = vb.z; Bs[lc + 3][r] = vb.w;
        }
        __syncthreads();

#pragma unroll
        for (int kk = 0; kk < 16; kk++) {
            float4 a0 = *(const float4*)&As[kk][ty * 4];
            float4 a1 = *(const float4*)&As[kk][64 + ty * 4];
            float4 b0 = *(const float4*)&Bs[kk][tx * 4];
            float4 b1 = *(const float4*)&Bs[kk][64 + tx * 4];
            float a[8] = {a0.x, a0.y, a0.z, a0.w, a1.x, a1.y, a1.z, a1.w};
            float b[8] = {b0.x, b0.y, b0.z, b0.w, b1.x, b1.y, b1.z, b1.w};
#pragma unroll
            for (int i = 0; i < 8; i++)
#pragma unroll
                for (int j = 0; j < 8; j++)
                    acc[i][j] += a[i] * b[j];
        }
        __syncthreads();
    }

    // Epilogue: vectorized stores + bias
#pragma unroll
    for (int ih = 0; ih < 2; ih++) {
#pragma unroll
        for (int i = 0; i < 4; i++) {
            int row = m0 + ih * 64 + ty * 4 + i;
#pragma unroll
            for (int jh = 0; jh < 2; jh++) {
                int col = n0 + jh * 64 + tx * 4;
                float4 bv = *(const float4*)&bias[col];
                float4 cv;
                cv.x = acc[ih * 4 + i][jh * 4 + 0] + bv.x;
                cv.y = acc[ih * 4 + i][jh * 4 + 1] + bv.y;
                cv.z = acc[ih * 4 + i][jh * 4 + 2] + bv.z;
                cv.w = acc[ih * 4 + i][jh * 4 + 3] + bv.w;
                *(float4*)&C[(size_t)row * N + col] = cv;
            }
        }
    }
}

// ---------------------------------------------------------------------------
// Flash attention, fp32, non-causal.
// Grid: (S/64 q-tiles, B*H).  Block: 256 threads. BQ=64, BK=32.
// Thread (qr = tid>>2, g = tid&3): owns query row qr of the tile,
// computes scores for 8 keys (cols g*8..g*8+7) per key tile,
// and accumulates O for 16 head-dims (g*16..g*16+15).
// Online softmax stats (m,l) reduced across the 4-thread quad via shfl.
// All shared memory STATIC (42 KB) — no attribute calls needed.
// Output layout [B][H][S][Dh] == reference's head-untransposed reshape.
// ---------------------------------------------------------------------------
__global__ __launch_bounds__(256) void attn_kernel(
    const float* __restrict__ qkv, float* __restrict__ outp)
{
    __shared__ float Qs[64 * 65];   // [qrow][dim]   (pad 1)
    __shared__ float Kt[64 * 33];   // [dim][key]    (32 keys, pad 1)
    __shared__ float Vs[32 * 68];   // [key][dim]    (float4-aligned rows)
    __shared__ float Ps[64 * 33];   // [qrow][key]

    const int tid = threadIdx.x;
    const int qt  = blockIdx.x;          // query tile
    const int bh  = blockIdx.y;          // b*16 + h
    const int b   = bh >> 4;
    const int h   = bh & 15;

    const size_t rowbase = (size_t)b * SEQ * QKVN;
    const int qcol = h * DHEAD;
    const int kcol = DMODEL + h * DHEAD;
    const int vcol = 2 * DMODEL + h * DHEAD;
    const int q0   = qt * 64;

    const int qr = tid >> 2;     // 0..63 query row
    const int g  = tid & 3;      // quad lane

    // --- Load Q tile once: 64 rows x 64 dims = 1024 float4 ---
#pragma unroll
    for (int i = 0; i < 4; i++) {
        int f  = i * 256 + tid;
        int r  = f >> 4;
        int c4 = (f & 15) << 2;
        float4 v = *(const float4*)&qkv[rowbase + (size_t)(q0 + r) * QKVN + qcol + c4];
        Qs[r * 65 + c4 + 0] = v.x; Qs[r * 65 + c4 + 1] = v.y;
        Qs[r * 65 + c4 + 2] = v.z; Qs[r * 65 + c4 + 3] = v.w;
    }

    float o[16];
#pragma unroll
    for (int d = 0; d < 16; d++) o[d] = 0.f;
    float m = -INFINITY;
    float l = 0.f;

    for (int t = 0; t < SEQ / 32; t++) {
        const int k0 = t * 32;
        __syncthreads();   // previous iteration's Kt/Vs/Ps fully consumed

        // --- Load K (transposed) and V tiles: 32 rows x 64 dims = 512 float4 each ---
#pragma unroll
        for (int i = 0; i < 2; i++) {
            int f  = i * 256 + tid;
            int r  = f >> 4;              // key index 0..31
            int c4 = (f & 15) << 2;       // head-dim base
            float4 kv = *(const float4*)&qkv[rowbase + (size_t)(k0 + r) * QKVN + kcol + c4];
            Kt[(c4 + 0) * 33 + r] = kv.x; Kt[(c4 + 1) * 33 + r] = kv.y;
            Kt[(c4 + 2) * 33 + r] = kv.z; Kt[(c4 + 3) * 33 + r] = kv.w;
            float4 vv = *(const float4*)&qkv[rowbase + (size_t)(k0 + r) * QKVN + vcol + c4];
            *(float4*)&Vs[r * 68 + c4] = vv;
        }
        __syncthreads();

        // --- Scores: s[j] = Q[qr,:] . K[g*8+j,:]  (dim-major inner) ---
        float s[8];
#pragma unroll
        for (int j = 0; j < 8; j++) s[j] = 0.f;
#pragma unroll 4
        for (int k = 0; k < 64; k++) {
            float qv = Qs[qr * 65 + k];
            const float* kr = &Kt[k * 33 + g * 8];
#pragma unroll
            for (int j = 0; j < 8; j++)
                s[j] += qv * kr[j];
        }
#pragma unroll
        for (int j = 0; j < 8; j++) s[j] *= 0.125f;   // 1/sqrt(64)

        // --- Online softmax update (quad reduction via shfl) ---
        float tmax = s[0];
#pragma unroll
        for (int j = 1; j < 8; j++) tmax = fmaxf(tmax, s[j]);
        tmax = fmaxf(tmax, __shfl_xor_sync(0xffffffffu, tmax, 1));
        tmax = fmaxf(tmax, __shfl_xor_sync(0xffffffffu, tmax, 2));
        float mnew = fmaxf(m, tmax);
        float corr = __expf(m - mnew);      // 0 on first tile (m = -inf)

        float lsum = 0.f;
#pragma unroll
        for (int j = 0; j < 8; j++) {
            float p = __expf(s[j] - mnew);
            Ps[qr * 33 + g * 8 + j] = p;
            lsum += p;
        }
        lsum += __shfl_xor_sync(0xffffffffu, lsum, 1);
        lsum += __shfl_xor_sync(0xffffffffu, lsum, 2);
        l = l * corr + lsum;
        m = mnew;
#pragma unroll
        for (int d = 0; d < 16; d++) o[d] *= corr;

        __syncwarp();   // Ps shared only within the quad (same warp)

        // --- PV: o[d] += sum_kc P[qr][kc] * V[kc][g*16+d] ---
#pragma unroll 4
        for (int kc = 0; kc < 32; kc++) {
            float p = Ps[qr * 33 + kc];
            const float4* vr = (const float4*)&Vs[kc * 68 + g * 16];
#pragma unroll
            for (int j4 = 0; j4 < 4; j4++) {
                float4 v = vr[j4];
                o[j4 * 4 + 0] += p * v.x;
                o[j4 * 4 + 1] += p * v.y;
                o[j4 * 4 + 2] += p * v.z;
                o[j4 * 4 + 3] += p * v.w;
            }
        }
    }

    // --- Finalize + store to [B][H][S][Dh] layout ---
    float inv = 1.0f / l;
    size_t obase = ((size_t)bh * SEQ + q0 + qr) * DHEAD + g * 16;
#pragma unroll
    for (int j4 = 0; j4 < 4; j4++) {
        float4 v;
        v.x = o[j4 * 4 + 0] * inv;
        v.y = o[j4 * 4 + 1] * inv;
        v.z = o[j4 * 4 + 2] * inv;
        v.w = o[j4 * 4 + 3] * inv;
        *(float4*)&outp[obase + j4 * 4] = v;
    }
}

// ---------------------------------------------------------------------------
// Launch
// ---------------------------------------------------------------------------
extern "C" void kernel_launch(void* const* d_in, const int* in_sizes, int n_in,
                              void* d_out, int out_size)
{
    const float* x     = (const float*)d_in[0];   // [2,2048,1024]
    const float* w_in  = (const float*)d_in[1];   // [3072,1024]
    const float* b_in  = (const float*)d_in[2];   // [3072]
    const float* w_out = (const float*)d_in[3];   // [1024,1024]
    const float* b_out = (const float*)d_in[4];   // [1024]
    float* out = (float*)d_out;

    float *qkv_p, *att_p;
    cudaGetSymbolAddress((void**)&qkv_p, g_qkv);
    cudaGetSymbolAddress((void**)&att_p, g_att);

    // 1) QKV = x @ w_in^T + b_in
    {
        dim3 grid(QKVN / 128, MROWS / 128);
        gemm_nt_bias<<<grid, 256>>>(x, w_in, b_in, qkv_p, MROWS, QKVN, DMODEL);
    }
    // 2) attention -> g_att in [B][H][S][Dh] (== reference reshape as [4096,1024])
    {
        dim3 grid(SEQ / 64, BATCH * NHEADS);
        attn_kernel<<<grid, 256>>>(qkv_p, att_p);
    }
    // 3) out = att @ w_out^T + b_out
    {
        dim3 grid(DMODEL / 128, MROWS / 128);
        gemm_nt_bias<<<grid, 256>>>(att_p, w_out, b_out, out, MROWS, DMODEL, DMODEL);
    }
}

// round 3
// speedup vs baseline: 5.0940x; 5.0940x over previous
#include <cuda_runtime.h>
#include <cuda_bf16.h>
#include <math.h>

// Problem constants
#define BATCH   2
#define SEQ     2048
#define DMODEL  1024
#define NHEADS  16
#define DHEAD   64
#define MROWS   (BATCH * SEQ)          // 4096
#define QKVN    (3 * DMODEL)           // 3072

// Scratch (device globals: allocation-free rule)
__device__ float g_qkv[(size_t)MROWS * QKVN];   // [4096, 3072]
__device__ float g_att[(size_t)MROWS * DMODEL]; // [B][H][S][Dh] flat == [4096,1024]

// ---------------------------------------------------------------------------
// tf32 helpers
// ---------------------------------------------------------------------------
__device__ __forceinline__ unsigned f2tf(float f) {
    unsigned r;
    asm("cvt.rna.tf32.f32 %0, %1;" : "=r"(r) : "f"(f));
    return r;
}

// D += A*B, m16n8k8 tf32. c[4] accumulates in place.
__device__ __forceinline__ void mma8(float c[4],
    unsigned a0, unsigned a1, unsigned a2, unsigned a3,
    unsigned b0, unsigned b1)
{
    asm volatile(
        "mma.sync.aligned.m16n8k8.row.col.f32.tf32.tf32.f32 "
        "{%0,%1,%2,%3}, {%4,%5,%6,%7}, {%8,%9}, {%0,%1,%2,%3};"
        : "+f"(c[0]), "+f"(c[1]), "+f"(c[2]), "+f"(c[3])
        : "r"(a0), "r"(a1), "r"(a2), "r"(a3), "r"(b0), "r"(b1));
}

// ---------------------------------------------------------------------------
// GEMM (NT) tf32: C[M,N] = A[M,K] @ B[N,K]^T + bias[N]
// 128x128 block, BK=16, 256 threads (8 warps), warp tile 64x32.
// Double-buffered smem, pad 20 (fragment loads conflict-free).
// M,N % 128 == 0, K % 16 == 0.
// ---------------------------------------------------------------------------
__global__ __launch_bounds__(256) void gemm_tf32(
    const float* __restrict__ A, const float* __restrict__ B,
    const float* __restrict__ bias, float* __restrict__ C,
    int M, int N, int K)
{
    __shared__ unsigned As[2][128][20];
    __shared__ unsigned Bs[2][128][20];

    const int tid  = threadIdx.x;
    const int warp = tid >> 5;
    const int lane = tid & 31;
    const int g    = lane >> 2;      // 0..7
    const int tg   = lane & 3;       // 0..3
    const int wm   = warp >> 2;      // 0..1  (m block of 64)
    const int wn   = warp & 3;       // 0..3  (n block of 32)

    const int m0 = blockIdx.y * 128;
    const int n0 = blockIdx.x * 128;

    const int lr = tid >> 2;          // 0..63 load row
    const int lc = (tid & 3) << 2;    // 0,4,8,12 load k-col

    float acc[4][4][4];
#pragma unroll
    for (int i = 0; i < 4; i++)
#pragma unroll
        for (int j = 0; j < 4; j++)
#pragma unroll
            for (int r = 0; r < 4; r++) acc[i][j][r] = 0.f;

    const float* Ap = A + (size_t)(m0 + lr) * K + lc;
    const float* Bp = B + (size_t)(n0 + lr) * K + lc;

    const int iters = K >> 4;

    // Preload tile 0
    {
#pragma unroll
        for (int h = 0; h < 2; h++) {
            float4 va = *(const float4*)(Ap + (size_t)h * 64 * K);
            int r = lr + h * 64;
            As[0][r][lc+0] = f2tf(va.x); As[0][r][lc+1] = f2tf(va.y);
            As[0][r][lc+2] = f2tf(va.z); As[0][r][lc+3] = f2tf(va.w);
            float4 vb = *(const float4*)(Bp + (size_t)h * 64 * K);
            Bs[0][r][lc+0] = f2tf(vb.x); Bs[0][r][lc+1] = f2tf(vb.y);
            Bs[0][r][lc+2] = f2tf(vb.z); Bs[0][r][lc+3] = f2tf(vb.w);
        }
    }
    __syncthreads();

    for (int it = 0; it < iters; it++) {
        const int buf = it & 1;
        // Prefetch next tile into the other buffer
        if (it + 1 < iters) {
            const int nb = buf ^ 1;
            const int k0 = (it + 1) << 4;
#pragma unroll
            for (int h = 0; h < 2; h++) {
                float4 va = *(const float4*)(Ap + (size_t)h * 64 * K + k0);
                int r = lr + h * 64;
                As[nb][r][lc+0] = f2tf(va.x); As[nb][r][lc+1] = f2tf(va.y);
                As[nb][r][lc+2] = f2tf(va.z); As[nb][r][lc+3] = f2tf(va.w);
                float4 vb = *(const float4*)(Bp + (size_t)h * 64 * K + k0);
                Bs[nb][r][lc+0] = f2tf(vb.x); Bs[nb][r][lc+1] = f2tf(vb.y);
                Bs[nb][r][lc+2] = f2tf(vb.z); Bs[nb][r][lc+3] = f2tf(vb.w);
            }
        }

        // Compute on current buffer: 2 k-steps of 8
#pragma unroll
        for (int ks = 0; ks < 2; ks++) {
            const int kk = ks * 8;
            unsigned a[4][4];
#pragma unroll
            for (int ma = 0; ma < 4; ma++) {
                int r = wm * 64 + ma * 16 + g;
                a[ma][0] = As[buf][r    ][kk + tg];
                a[ma][1] = As[buf][r + 8][kk + tg];
                a[ma][2] = As[buf][r    ][kk + tg + 4];
                a[ma][3] = As[buf][r + 8][kk + tg + 4];
            }
            unsigned b[4][2];
#pragma unroll
            for (int na = 0; na < 4; na++) {
                int n = wn * 32 + na * 8 + g;
                b[na][0] = Bs[buf][n][kk + tg];
                b[na][1] = Bs[buf][n][kk + tg + 4];
            }
#pragma unroll
            for (int ma = 0; ma < 4; ma++)
#pragma unroll
                for (int na = 0; na < 4; na++)
                    mma8(acc[ma][na], a[ma][0], a[ma][1], a[ma][2], a[ma][3],
                         b[na][0], b[na][1]);
        }
        __syncthreads();
    }

    // Epilogue: accum layout c0,c1 = (row g, cols 2tg,2tg+1); c2,c3 = row g+8.
#pragma unroll
    for (int ma = 0; ma < 4; ma++) {
        int row0 = m0 + wm * 64 + ma * 16 + g;
#pragma unroll
        for (int na = 0; na < 4; na++) {
            int col = n0 + wn * 32 + na * 8 + tg * 2;
            float2 bv = *(const float2*)&bias[col];
            float2 v0 = { acc[ma][na][0] + bv.x, acc[ma][na][1] + bv.y };
            float2 v1 = { acc[ma][na][2] + bv.x, acc[ma][na][3] + bv.y };
            *(float2*)&C[(size_t)row0 * N + col]       = v0;
            *(float2*)&C[(size_t)(row0 + 8) * N + col] = v1;
        }
    }
}

// ---------------------------------------------------------------------------
// Flash attention, tf32 tensor cores. Grid: (S/64, B*H). Block: 128 (4 warps).
// Warp w owns q-rows [w*16, w*16+16). BK=32 keys per tile.
// Scores via mma (A=Q rowmajor, B=K as col-major of K^T), softmax in accum
// layout (rows g / g+8, quad shfl reduce), P through smem (warp-private rows),
// PV via mma (A=P, B=V read column-wise, pad 72 => conflict-free).
// 44.5 KB static smem. Output layout [B][H][S][Dh].
// ---------------------------------------------------------------------------
__global__ __launch_bounds__(128) void attn_tf32(
    const float* __restrict__ qkv, float* __restrict__ outp)
{
    __shared__ unsigned Qs[64][68];
    __shared__ unsigned Ks[32][68];
    __shared__ unsigned Vs[32][72];
    __shared__ unsigned Ps[64][36];

    const int tid  = threadIdx.x;
    const int warp = tid >> 5;
    const int lane = tid & 31;
    const int g    = lane >> 2;
    const int tg   = lane & 3;
    const int wq0  = warp * 16;          // warp's q-row base in tile

    const int qt = blockIdx.x;
    const int bh = blockIdx.y;
    const int b  = bh >> 4;
    const int h  = bh & 15;

    const size_t rowbase = (size_t)b * SEQ * QKVN;
    const int qcol = h * DHEAD;
    const int kcol = DMODEL + h * DHEAD;
    const int vcol = 2 * DMODEL + h * DHEAD;
    const int q0   = qt * 64;

    // --- Load Q tile: 64x64 floats = 1024 float4, 8 per thread ---
#pragma unroll
    for (int i = 0; i < 8; i++) {
        int f  = i * 128 + tid;
        int r  = f >> 4;
        int c4 = (f & 15) << 2;
        float4 v = *(const float4*)&qkv[rowbase + (size_t)(q0 + r) * QKVN + qcol + c4];
        Qs[r][c4+0] = f2tf(v.x); Qs[r][c4+1] = f2tf(v.y);
        Qs[r][c4+2] = f2tf(v.z); Qs[r][c4+3] = f2tf(v.w);
    }

    float o[8][4];
#pragma unroll
    for (int i = 0; i < 8; i++)
#pragma unroll
        for (int j = 0; j < 4; j++) o[i][j] = 0.f;
    float mx0 = -INFINITY, mx1 = -INFINITY;
    float l0 = 0.f, l1 = 0.f;

    for (int t = 0; t < SEQ / 32; t++) {
        const int k0 = t * 32;
        __syncthreads();   // previous tile's K/V fully consumed (and Q visible at t=0)

        // --- Load K,V tiles: 32x64 each = 512 float4 each, 4 per thread ---
#pragma unroll
        for (int i = 0; i < 4; i++) {
            int f  = i * 128 + tid;
            int r  = f >> 4;
            int c4 = (f & 15) << 2;
            float4 kv = *(const float4*)&qkv[rowbase + (size_t)(k0 + r) * QKVN + kcol + c4];
            Ks[r][c4+0] = f2tf(kv.x); Ks[r][c4+1] = f2tf(kv.y);
            Ks[r][c4+2] = f2tf(kv.z); Ks[r][c4+3] = f2tf(kv.w);
            float4 vv = *(const float4*)&qkv[rowbase + (size_t)(k0 + r) * QKVN + vcol + c4];
            Vs[r][c4+0] = f2tf(vv.x); Vs[r][c4+1] = f2tf(vv.y);
            Vs[r][c4+2] = f2tf(vv.z); Vs[r][c4+3] = f2tf(vv.w);
        }
        __syncthreads();

        // --- Scores: S[16q x 32k] = Q @ K^T, 8 k-steps x 4 n-atoms ---
        float s[4][4];
#pragma unroll
        for (int na = 0; na < 4; na++)
#pragma unroll
            for (int r = 0; r < 4; r++) s[na][r] = 0.f;

#pragma unroll
        for (int ks = 0; ks < 8; ks++) {
            const int kk = ks * 8;
            unsigned a0 = Qs[wq0 + g    ][kk + tg];
            unsigned a1 = Qs[wq0 + g + 8][kk + tg];
            unsigned a2 = Qs[wq0 + g    ][kk + tg + 4];
            unsigned a3 = Qs[wq0 + g + 8][kk + tg + 4];
#pragma unroll
            for (int na = 0; na < 4; na++) {
                unsigned b0 = Ks[na * 8 + g][kk + tg];
                unsigned b1 = Ks[na * 8 + g][kk + tg + 4];
                mma8(s[na], a0, a1, a2, a3, b0, b1);
            }
        }

        // --- Online softmax. Thread holds rows (g) via c0,c1 and (g+8) via c2,c3 ---
        float t0 = -INFINITY, t1 = -INFINITY;
#pragma unroll
        for (int na = 0; na < 4; na++) {
            s[na][0] *= 0.125f; s[na][1] *= 0.125f;
            s[na][2] *= 0.125f; s[na][3] *= 0.125f;
            t0 = fmaxf(t0, fmaxf(s[na][0], s[na][1]));
            t1 = fmaxf(t1, fmaxf(s[na][2], s[na][3]));
        }
        t0 = fmaxf(t0, __shfl_xor_sync(0xffffffffu, t0, 1));
        t0 = fmaxf(t0, __shfl_xor_sync(0xffffffffu, t0, 2));
        t1 = fmaxf(t1, __shfl_xor_sync(0xffffffffu, t1, 1));
        t1 = fmaxf(t1, __shfl_xor_sync(0xffffffffu, t1, 2));

        float mn0 = fmaxf(mx0, t0), mn1 = fmaxf(mx1, t1);
        float corr0 = __expf(mx0 - mn0), corr1 = __expf(mx1 - mn1);

        float ls0 = 0.f, ls1 = 0.f;
#pragma unroll
        for (int na = 0; na < 4; na++) {
            float p0 = __expf(s[na][0] - mn0);
            float p1 = __expf(s[na][1] - mn0);
            float p2 = __expf(s[na][2] - mn1);
            float p3 = __expf(s[na][3] - mn1);
            ls0 += p0 + p1; ls1 += p2 + p3;
            int c = na * 8 + tg * 2;
            Ps[wq0 + g    ][c    ] = f2tf(p0);
            Ps[wq0 + g    ][c + 1] = f2tf(p1);
            Ps[wq0 + g + 8][c    ] = f2tf(p2);
            Ps[wq0 + g + 8][c + 1] = f2tf(p3);
        }
        ls0 += __shfl_xor_sync(0xffffffffu, ls0, 1);
        ls0 += __shfl_xor_sync(0xffffffffu, ls0, 2);
        ls1 += __shfl_xor_sync(0xffffffffu, ls1, 1);
        ls1 += __shfl_xor_sync(0xffffffffu, ls1, 2);
        l0 = l0 * corr0 + ls0;  mx0 = mn0;
        l1 = l1 * corr1 + ls1;  mx1 = mn1;

#pragma unroll
        for (int na = 0; na < 8; na++) {
            o[na][0] *= corr0; o[na][1] *= corr0;
            o[na][2] *= corr1; o[na][3] *= corr1;
        }

        __syncwarp();   // P rows are warp-private; order STS->LDS across lanes

        // --- PV: O[16q x 64d] += P[16 x 32] @ V[32 x 64], 4 k-steps x 8 n-atoms ---
#pragma unroll
        for (int ks = 0; ks < 4; ks++) {
            const int kk = ks * 8;
            unsigned a0 = Ps[wq0 + g    ][kk + tg];
            unsigned a1 = Ps[wq0 + g + 8][kk + tg];
            unsigned a2 = Ps[wq0 + g    ][kk + tg + 4];
            unsigned a3 = Ps[wq0 + g + 8][kk + tg + 4];
#pragma unroll
            for (int na = 0; na < 8; na++) {
                unsigned b0 = Vs[kk + tg    ][na * 8 + g];
                unsigned b1 = Vs[kk + tg + 4][na * 8 + g];
                mma8(o[na], a0, a1, a2, a3, b0, b1);
            }
        }
    }

    // --- Finalize + store to [B][H][S][Dh] ---
    float inv0 = 1.0f / l0, inv1 = 1.0f / l1;
    int row0 = q0 + wq0 + g;
    size_t base0 = ((size_t)bh * SEQ + row0)     * DHEAD;
    size_t base1 = ((size_t)bh * SEQ + row0 + 8) * DHEAD;
#pragma unroll
    for (int na = 0; na < 8; na++) {
        int c = na * 8 + tg * 2;
        float2 v0 = { o[na][0] * inv0, o[na][1] * inv0 };
        float2 v1 = { o[na][2] * inv1, o[na][3] * inv1 };
        *(float2*)&outp[base0 + c] = v0;
        *(float2*)&outp[base1 + c] = v1;
    }
}

// ---------------------------------------------------------------------------
// Launch
// ---------------------------------------------------------------------------
extern "C" void kernel_launch(void* const* d_in, const int* in_sizes, int n_in,
                              void* d_out, int out_size)
{
    const float* x     = (const float*)d_in[0];   // [2,2048,1024]
    const float* w_in  = (const float*)d_in[1];   // [3072,1024]
    const float* b_in  = (const float*)d_in[2];   // [3072]
    const float* w_out = (const float*)d_in[3];   // [1024,1024]
    const float* b_out = (const float*)d_in[4];   // [1024]
    float* out = (float*)d_out;

    float *qkv_p, *att_p;
    cudaGetSymbolAddress((void**)&qkv_p, g_qkv);
    cudaGetSymbolAddress((void**)&att_p, g_att);

    // 1) QKV = x @ w_in^T + b_in
    {
        dim3 grid(QKVN / 128, MROWS / 128);
        gemm_tf32<<<grid, 256>>>(x, w_in, b_in, qkv_p, MROWS, QKVN, DMODEL);
    }
    // 2) attention -> g_att in [B][H][S][Dh] (== reference reshape as [4096,1024])
    {
        dim3 grid(SEQ / 64, BATCH * NHEADS);
        attn_tf32<<<grid, 128>>>(qkv_p, att_p);
    }
    // 3) out = att @ w_out^T + b_out
    {
        dim3 grid(DMODEL / 128, MROWS / 128);
        gemm_tf32<<<grid, 256>>>(att_p, w_out, b_out, out, MROWS, DMODEL, DMODEL);
    }
}

// round 4
// speedup vs baseline: 6.4481x; 1.2658x over previous
#include <cuda_runtime.h>
#include <cuda_bf16.h>
#include <math.h>

// Problem constants
#define BATCH   2
#define SEQ     2048
#define DMODEL  1024
#define NHEADS  16
#define DHEAD   64
#define MROWS   (BATCH * SEQ)          // 4096
#define QKVN    (3 * DMODEL)           // 3072

// Scratch (device globals: allocation-free rule)
__device__ float g_qkv[(size_t)MROWS * QKVN];   // [4096, 3072] tf32-rounded
__device__ float g_att[(size_t)MROWS * DMODEL]; // [B][H][S][Dh] tf32-rounded
__device__ float g_xr [(size_t)MROWS * DMODEL];     // x rounded
__device__ float g_wir[(size_t)QKVN * DMODEL];      // w_in rounded
__device__ float g_wor[(size_t)DMODEL * DMODEL];    // w_out rounded

// ---------------------------------------------------------------------------
// helpers
// ---------------------------------------------------------------------------
__device__ __forceinline__ unsigned f2tf(float f) {
    unsigned r;
    asm("cvt.rna.tf32.f32 %0, %1;" : "=r"(r) : "f"(f));
    return r;
}
__device__ __forceinline__ float roundtf(float f) {
    return __uint_as_float(f2tf(f));
}
__device__ __forceinline__ void cp16(void* sdst, const void* gsrc) {
    unsigned s = (unsigned)__cvta_generic_to_shared(sdst);
    asm volatile("cp.async.cg.shared.global [%0], [%1], 16;" :: "r"(s), "l"(gsrc) : "memory");
}
#define CP_COMMIT()  asm volatile("cp.async.commit_group;" ::: "memory")
#define CP_WAIT0()   asm volatile("cp.async.wait_group 0;" ::: "memory")
#define CP_WAIT1()   asm volatile("cp.async.wait_group 1;" ::: "memory")

// D += A*B, m16n8k8 tf32 (raw fp32 bits, values pre-rounded to tf32)
__device__ __forceinline__ void mma8(float c[4],
    unsigned a0, unsigned a1, unsigned a2, unsigned a3,
    unsigned b0, unsigned b1)
{
    asm volatile(
        "mma.sync.aligned.m16n8k8.row.col.f32.tf32.tf32.f32 "
        "{%0,%1,%2,%3}, {%4,%5,%6,%7}, {%8,%9}, {%0,%1,%2,%3};"
        : "+f"(c[0]), "+f"(c[1]), "+f"(c[2]), "+f"(c[3])
        : "r"(a0), "r"(a1), "r"(a2), "r"(a3), "r"(b0), "r"(b1));
}

// ---------------------------------------------------------------------------
// Pre-round fp32 -> tf32-representable fp32 (vectorized)
// ---------------------------------------------------------------------------
__global__ void round_tf32_k(const float* __restrict__ s, float* __restrict__ d, int n4)
{
    int i = blockIdx.x * blockDim.x + threadIdx.x;
    if (i < n4) {
        float4 v = ((const float4*)s)[i];
        v.x = roundtf(v.x); v.y = roundtf(v.y);
        v.z = roundtf(v.z); v.w = roundtf(v.w);
        ((float4*)d)[i] = v;
    }
}

// ---------------------------------------------------------------------------
// GEMM (NT) tf32: C[M,N] = A[M,K] @ B[N,K]^T + bias[N]
// A,B values must be tf32-representable. cp.async double-buffered.
// 128x128 block, BK=16, 256 threads (8 warps), warp tile 64x32.
// round_out: epilogue rounds C to tf32-representable (for intermediates).
// ---------------------------------------------------------------------------
__global__ __launch_bounds__(256) void gemm_tf32(
    const float* __restrict__ A, const float* __restrict__ B,
    const float* __restrict__ bias, float* __restrict__ C,
    int M, int N, int K, int round_out)
{
    __shared__ __align__(16) float As[2][128][20];
    __shared__ __align__(16) float Bs[2][128][20];

    const int tid  = threadIdx.x;
    const int warp = tid >> 5;
    const int lane = tid & 31;
    const int g    = lane >> 2;      // 0..7
    const int tg   = lane & 3;       // 0..3
    const int wm   = warp >> 2;      // 0..1
    const int wn   = warp & 3;       // 0..3

    const int m0 = blockIdx.y * 128;
    const int n0 = blockIdx.x * 128;

    const int lr  = tid >> 2;          // 0..63 load row
    const int lc4 = (tid & 3) << 2;    // 0,4,8,12

    float acc[4][4][4];
#pragma unroll
    for (int i = 0; i < 4; i++)
#pragma unroll
        for (int j = 0; j < 4; j++)
#pragma unroll
            for (int r = 0; r < 4; r++) acc[i][j][r] = 0.f;

    const float* Ap = A + (size_t)(m0 + lr) * K + lc4;
    const float* Bp = B + (size_t)(n0 + lr) * K + lc4;

    const int iters = K >> 4;

    // Preload tile 0
#pragma unroll
    for (int h = 0; h < 2; h++) {
        cp16(&As[0][lr + h * 64][lc4], Ap + (size_t)h * 64 * K);
        cp16(&Bs[0][lr + h * 64][lc4], Bp + (size_t)h * 64 * K);
    }
    CP_COMMIT();

    for (int it = 0; it < iters; it++) {
        const int buf = it & 1;
        if (it + 1 < iters) {
            const int nb = buf ^ 1;
            const int k0 = (it + 1) << 4;
#pragma unroll
            for (int h = 0; h < 2; h++) {
                cp16(&As[nb][lr + h * 64][lc4], Ap + (size_t)h * 64 * K + k0);
                cp16(&Bs[nb][lr + h * 64][lc4], Bp + (size_t)h * 64 * K + k0);
            }
            CP_COMMIT();
            CP_WAIT1();
        } else {
            CP_WAIT0();
        }
        __syncthreads();

#pragma unroll
        for (int ks = 0; ks < 2; ks++) {
            const int kk = ks * 8;
            unsigned a[4][4];
#pragma unroll
            for (int ma = 0; ma < 4; ma++) {
                int r = wm * 64 + ma * 16 + g;
                a[ma][0] = __float_as_uint(As[buf][r    ][kk + tg]);
                a[ma][1] = __float_as_uint(As[buf][r + 8][kk + tg]);
                a[ma][2] = __float_as_uint(As[buf][r    ][kk + tg + 4]);
                a[ma][3] = __float_as_uint(As[buf][r + 8][kk + tg + 4]);
            }
            unsigned b[4][2];
#pragma unroll
            for (int na = 0; na < 4; na++) {
                int n = wn * 32 + na * 8 + g;
                b[na][0] = __float_as_uint(Bs[buf][n][kk + tg]);
                b[na][1] = __float_as_uint(Bs[buf][n][kk + tg + 4]);
            }
#pragma unroll
            for (int ma = 0; ma < 4; ma++)
#pragma unroll
                for (int na = 0; na < 4; na++)
                    mma8(acc[ma][na], a[ma][0], a[ma][1], a[ma][2], a[ma][3],
                         b[na][0], b[na][1]);
        }
        __syncthreads();
    }

    // Epilogue
#pragma unroll
    for (int ma = 0; ma < 4; ma++) {
        int row0 = m0 + wm * 64 + ma * 16 + g;
#pragma unroll
        for (int na = 0; na < 4; na++) {
            int col = n0 + wn * 32 + na * 8 + tg * 2;
            float2 bv = *(const float2*)&bias[col];
            float2 v0 = { acc[ma][na][0] + bv.x, acc[ma][na][1] + bv.y };
            float2 v1 = { acc[ma][na][2] + bv.x, acc[ma][na][3] + bv.y };
            if (round_out) {
                v0.x = roundtf(v0.x); v0.y = roundtf(v0.y);
                v1.x = roundtf(v1.x); v1.y = roundtf(v1.y);
            }
            *(float2*)&C[(size_t)row0 * N + col]       = v0;
            *(float2*)&C[(size_t)(row0 + 8) * N + col] = v1;
        }
    }
}

// ---------------------------------------------------------------------------
// Flash attention, tf32. Grid: (S/64, B*H). Block: 128 (4 warps).
// Q fragments held in registers for the whole KV loop (loop-invariant).
// K/V tiles (BK=32) double-buffered via cp.async.
// Shared memory manually carved (44 KB static); Q staging region reused.
// Output layout [B][H][S][Dh] == reference's head-untransposed reshape.
// ---------------------------------------------------------------------------
#define OFF_K   0            // [2][32][68]  -> 4352 floats
#define OFF_V   4352         // [2][32][72]  -> 4608 floats
#define OFF_P   8960         // [64][36]     -> 2304 floats
#define SM_FLT  11264        // 45056 bytes

__global__ __launch_bounds__(128) void attn_tf32(
    const float* __restrict__ qkv, float* __restrict__ outp)
{
    __shared__ __align__(16) float smf[SM_FLT];

    const int tid  = threadIdx.x;
    const int warp = tid >> 5;
    const int lane = tid & 31;
    const int g    = lane >> 2;
    const int tg   = lane & 3;
    const int wq0  = warp * 16;

    const int qt = blockIdx.x;
    const int bh = blockIdx.y;
    const int b  = bh >> 4;
    const int h  = bh & 15;

    const size_t rowbase = (size_t)b * SEQ * QKVN;
    const int qcol = h * DHEAD;
    const int kcol = DMODEL + h * DHEAD;
    const int vcol = 2 * DMODEL + h * DHEAD;
    const int q0   = qt * 64;

    // --- Phase A: stage Q tile in smem (reusing K/V region), pull to regs ---
#pragma unroll
    for (int i = 0; i < 8; i++) {
        int f  = i * 128 + tid;
        int r  = f >> 4;
        int c4 = (f & 15) << 2;
        cp16(&smf[r * 68 + c4],
             &qkv[rowbase + (size_t)(q0 + r) * QKVN + qcol + c4]);
    }
    CP_COMMIT();
    CP_WAIT0();
    __syncthreads();

    unsigned qa[8][4];
#pragma unroll
    for (int ks = 0; ks < 8; ks++) {
        const int kk = ks * 8;
        qa[ks][0] = __float_as_uint(smf[(wq0 + g    ) * 68 + kk + tg]);
        qa[ks][1] = __float_as_uint(smf[(wq0 + g + 8) * 68 + kk + tg]);
        qa[ks][2] = __float_as_uint(smf[(wq0 + g    ) * 68 + kk + tg + 4]);
        qa[ks][3] = __float_as_uint(smf[(wq0 + g + 8) * 68 + kk + tg + 4]);
    }
    __syncthreads();   // all Q reads done before K/V cp.async overwrites region

    float o[8][4];
#pragma unroll
    for (int i = 0; i < 8; i++)
#pragma unroll
        for (int j = 0; j < 4; j++) o[i][j] = 0.f;
    float mx0 = -INFINITY, mx1 = -INFINITY;
    float l0 = 0.f, l1 = 0.f;

    // --- Prefetch KV tile 0 into buffer 0 ---
#pragma unroll
    for (int i = 0; i < 4; i++) {
        int f  = i * 128 + tid;
        int r  = f >> 4;
        int c4 = (f & 15) << 2;
        cp16(&smf[OFF_K + r * 68 + c4], &qkv[rowbase + (size_t)r * QKVN + kcol + c4]);
        cp16(&smf[OFF_V + r * 72 + c4], &qkv[rowbase + (size_t)r * QKVN + vcol + c4]);
    }
    CP_COMMIT();

    const int NT = SEQ / 32;
    for (int t = 0; t < NT; t++) {
        const int buf = t & 1;
        const int kbase = OFF_K + buf * 2176;   // 32*68
        const int vbase = OFF_V + buf * 2304;   // 32*72

        if (t + 1 < NT) {
            const int nb = buf ^ 1;
            const int nk0 = (t + 1) * 32;
#pragma unroll
            for (int i = 0; i < 4; i++) {
                int f  = i * 128 + tid;
                int r  = f >> 4;
                int c4 = (f & 15) << 2;
                cp16(&smf[OFF_K + nb * 2176 + r * 68 + c4],
                     &qkv[rowbase + (size_t)(nk0 + r) * QKVN + kcol + c4]);
                cp16(&smf[OFF_V + nb * 2304 + r * 72 + c4],
                     &qkv[rowbase + (size_t)(nk0 + r) * QKVN + vcol + c4]);
            }
            CP_COMMIT();
            CP_WAIT1();
        } else {
            CP_WAIT0();
        }
        __syncthreads();

        // --- Scores: S[16q x 32k] = Q @ K^T ---
        float s[4][4];
#pragma unroll
        for (int na = 0; na < 4; na++)
#pragma unroll
            for (int r = 0; r < 4; r++) s[na][r] = 0.f;

#pragma unroll
        for (int ks = 0; ks < 8; ks++) {
            const int kk = ks * 8;
#pragma unroll
            for (int na = 0; na < 4; na++) {
                unsigned b0 = __float_as_uint(smf[kbase + (na * 8 + g) * 68 + kk + tg]);
                unsigned b1 = __float_as_uint(smf[kbase + (na * 8 + g) * 68 + kk + tg + 4]);
                mma8(s[na], qa[ks][0], qa[ks][1], qa[ks][2], qa[ks][3], b0, b1);
            }
        }

        // --- Online softmax (rows g and g+8, quad shfl reduce) ---
        float t0 = -INFINITY, t1 = -INFINITY;
#pragma unroll
        for (int na = 0; na < 4; na++) {
            s[na][0] *= 0.125f; s[na][1] *= 0.125f;
            s[na][2] *= 0.125f; s[na][3] *= 0.125f;
            t0 = fmaxf(t0, fmaxf(s[na][0], s[na][1]));
            t1 = fmaxf(t1, fmaxf(s[na][2], s[na][3]));
        }
        t0 = fmaxf(t0, __shfl_xor_sync(0xffffffffu, t0, 1));
        t0 = fmaxf(t0, __shfl_xor_sync(0xffffffffu, t0, 2));
        t1 = fmaxf(t1, __shfl_xor_sync(0xffffffffu, t1, 1));
        t1 = fmaxf(t1, __shfl_xor_sync(0xffffffffu, t1, 2));

        float mn0 = fmaxf(mx0, t0), mn1 = fmaxf(mx1, t1);
        float corr0 = __expf(mx0 - mn0), corr1 = __expf(mx1 - mn1);

        float ls0 = 0.f, ls1 = 0.f;
#pragma unroll
        for (int na = 0; na < 4; na++) {
            float p0 = __expf(s[na][0] - mn0);
            float p1 = __expf(s[na][1] - mn0);
            float p2 = __expf(s[na][2] - mn1);
            float p3 = __expf(s[na][3] - mn1);
            ls0 += p0 + p1; ls1 += p2 + p3;
            int c = na * 8 + tg * 2;
            smf[OFF_P + (wq0 + g    ) * 36 + c    ] = __uint_as_float(f2tf(p0));
            smf[OFF_P + (wq0 + g    ) * 36 + c + 1] = __uint_as_float(f2tf(p1));
            smf[OFF_P + (wq0 + g + 8) * 36 + c    ] = __uint_as_float(f2tf(p2));
            smf[OFF_P + (wq0 + g + 8) * 36 + c + 1] = __uint_as_float(f2tf(p3));
        }
        ls0 += __shfl_xor_sync(0xffffffffu, ls0, 1);
        ls0 += __shfl_xor_sync(0xffffffffu, ls0, 2);
        ls1 += __shfl_xor_sync(0xffffffffu, ls1, 1);
        ls1 += __shfl_xor_sync(0xffffffffu, ls1, 2);
        l0 = l0 * corr0 + ls0;  mx0 = mn0;
        l1 = l1 * corr1 + ls1;  mx1 = mn1;

#pragma unroll
        for (int na = 0; na < 8; na++) {
            o[na][0] *= corr0; o[na][1] *= corr0;
            o[na][2] *= corr1; o[na][3] *= corr1;
        }

        __syncwarp();   // P rows warp-private: order STS -> LDS across lanes

        // --- PV: O[16q x 64d] += P[16 x 32] @ V[32 x 64] ---
#pragma unroll
        for (int ks = 0; ks < 4; ks++) {
            const int kk = ks * 8;
            unsigned a0 = __float_as_uint(smf[OFF_P + (wq0 + g    ) * 36 + kk + tg]);
            unsigned a1 = __float_as_uint(smf[OFF_P + (wq0 + g + 8) * 36 + kk + tg]);
            unsigned a2 = __float_as_uint(smf[OFF_P + (wq0 + g    ) * 36 + kk + tg + 4]);
            unsigned a3 = __float_as_uint(smf[OFF_P + (wq0 + g + 8) * 36 + kk + tg + 4]);
#pragma unroll
            for (int na = 0; na < 8; na++) {
                unsigned b0 = __float_as_uint(smf[vbase + (kk + tg    ) * 72 + na * 8 + g]);
                unsigned b1 = __float_as_uint(smf[vbase + (kk + tg + 4) * 72 + na * 8 + g]);
                mma8(o[na], a0, a1, a2, a3, b0, b1);
            }
        }
        __syncthreads();   // all warps done with buf before its next overwrite
    }

    // --- Finalize + store (rounded: feeds final tf32 GEMM) ---
    float inv0 = 1.0f / l0, inv1 = 1.0f / l1;
    int row0 = q0 + wq0 + g;
    size_t base0 = ((size_t)bh * SEQ + row0)     * DHEAD;
    size_t base1 = ((size_t)bh * SEQ + row0 + 8) * DHEAD;
#pragma unroll
    for (int na = 0; na < 8; na++) {
        int c = na * 8 + tg * 2;
        float2 v0 = { roundtf(o[na][0] * inv0), roundtf(o[na][1] * inv0) };
        float2 v1 = { roundtf(o[na][2] * inv1), roundtf(o[na][3] * inv1) };
        *(float2*)&outp[base0 + c] = v0;
        *(float2*)&outp[base1 + c] = v1;
    }
}

// ---------------------------------------------------------------------------
// Launch
// ---------------------------------------------------------------------------
extern "C" void kernel_launch(void* const* d_in, const int* in_sizes, int n_in,
                              void* d_out, int out_size)
{
    const float* x     = (const float*)d_in[0];   // [2,2048,1024]
    const float* w_in  = (const float*)d_in[1];   // [3072,1024]
    const float* b_in  = (const float*)d_in[2];   // [3072]
    const float* w_out = (const float*)d_in[3];   // [1024,1024]
    const float* b_out = (const float*)d_in[4];   // [1024]
    float* out = (float*)d_out;

    float *qkv_p, *att_p, *xr_p, *wir_p, *wor_p;
    cudaGetSymbolAddress((void**)&qkv_p, g_qkv);
    cudaGetSymbolAddress((void**)&att_p, g_att);
    cudaGetSymbolAddress((void**)&xr_p,  g_xr);
    cudaGetSymbolAddress((void**)&wir_p, g_wir);
    cudaGetSymbolAddress((void**)&wor_p, g_wor);

    // 0) Round inputs to tf32-representable fp32
    {
        int n4x = (MROWS * DMODEL) / 4;       // 1,048,576
        int n4wi = (QKVN * DMODEL) / 4;       //   786,432
        int n4wo = (DMODEL * DMODEL) / 4;     //   262,144
        round_tf32_k<<<(n4x  + 255) / 256, 256>>>(x,     xr_p,  n4x);
        round_tf32_k<<<(n4wi + 255) / 256, 256>>>(w_in,  wir_p, n4wi);
        round_tf32_k<<<(n4wo + 255) / 256, 256>>>(w_out, wor_p, n4wo);
    }
    // 1) QKV = x @ w_in^T + b_in   (epilogue rounds -> tf32-representable)
    {
        dim3 grid(QKVN / 128, MROWS / 128);
        gemm_tf32<<<grid, 256>>>(xr_p, wir_p, b_in, qkv_p, MROWS, QKVN, DMODEL, 1);
    }
    // 2) attention -> g_att in [B][H][S][Dh]
    {
        dim3 grid(SEQ / 64, BATCH * NHEADS);
        attn_tf32<<<grid, 128>>>(qkv_p, att_p);
    }
    // 3) out = att @ w_out^T + b_out  (full fp32 output)
    {
        dim3 grid(DMODEL / 128, MROWS / 128);
        gemm_tf32<<<grid, 256>>>(att_p, wor_p, b_out, out, MROWS, DMODEL, DMODEL, 0);
    }
}